// round 14
// baseline (speedup 1.0000x reference)
#include <cuda_runtime.h>
#include <cuda_bf16.h>
#include <cstdint>

// ---------------- problem constants ----------------
#define BN    32
#define OO    144
#define CP    26
#define GT    256
#define HD    128
#define AOUT  28
#define NPAIR 10440
#define TM    128            // pairs per CTA tile
#define NTILE 82             // ceil(10440/128)
#define PADP  (NTILE*TM)     // 10496

// smem layout (bytes)
#define ASTR  264            // bf16 elems per A row (256 + 8 pad -> +16B skew)
#define BSTR  80             // bytes per B row (64B data + 16B pad)
#define SM_AH 0
#define SM_AL (128*ASTR*2)            // 67584
#define SM_B  (2*128*ASTR*2)          // 135168
#define BTERM (256*BSTR)              // 20480 (one term, one buffer)
#define BBUF  (2*BTERM)               // 40960 (hi+lo)
#define SM_PART (SM_B + 2*BBUF)       // 217088
#define SMTOT   (SM_PART + 2048)      // 219136

typedef unsigned long long u64;

// ---------------- device scratch ----------------
__device__ float g_u[BN*OO*GT];
__device__ float g_v[BN*OO*GT];
__device__ float g_base[BN*GT];
__device__ int   g_pa[PADP];
__device__ int   g_pb[PADP];
__device__ float g_partial[BN*NTILE*GT];
__device__ __nv_bfloat16 g_Bh[3*GT*GT];   // W^T hi, [l][n][k] (K-major)
__device__ __nv_bfloat16 g_Bl[3*GT*GT];   // W^T lo

// ---------------- helpers ----------------
__device__ __forceinline__ uint32_t smem_u32(const void* p) {
    uint32_t a;
    asm("{ .reg .u64 t; cvta.to.shared.u64 t, %1; cvt.u32.u64 %0, t; }" : "=r"(a) : "l"(p));
    return a;
}
__device__ __forceinline__ uint32_t pack2(__nv_bfloat16 a, __nv_bfloat16 b) {
    return (uint32_t)__bfloat16_as_ushort(a) | ((uint32_t)__bfloat16_as_ushort(b) << 16);
}
__device__ __forceinline__ void ldsm4(uint32_t& r0, uint32_t& r1, uint32_t& r2, uint32_t& r3,
                                      uint32_t addr) {
    asm volatile("ldmatrix.sync.aligned.m8n8.x4.shared.b16 {%0,%1,%2,%3}, [%4];"
        : "=r"(r0), "=r"(r1), "=r"(r2), "=r"(r3) : "r"(addr));
}
__device__ __forceinline__ void mma16816(float* d, const uint32_t* a, const uint32_t* b) {
    asm volatile("mma.sync.aligned.m16n8k16.row.col.f32.bf16.bf16.f32 "
        "{%0,%1,%2,%3}, {%4,%5,%6,%7}, {%8,%9}, {%0,%1,%2,%3};"
        : "+f"(d[0]), "+f"(d[1]), "+f"(d[2]), "+f"(d[3])
        : "r"(a[0]), "r"(a[1]), "r"(a[2]), "r"(a[3]), "r"(b[0]), "r"(b[1]));
}
__device__ __forceinline__ void cpa16(uint32_t dst, const void* src) {
    asm volatile("cp.async.cg.shared.global [%0], [%1], 16;" :: "r"(dst), "l"(src));
}
#define CP_COMMIT() asm volatile("cp.async.commit_group;" ::: "memory")

// ---------------- prep kernels ----------------
__global__ void pairs_kernel() {
    int p = blockIdx.x * blockDim.x + threadIdx.x;
    if (p >= PADP) return;
    if (p >= NPAIR) { g_pa[p] = 0; g_pb[p] = 0; return; }
    int a = (int)((sqrtf(8.0f * (float)p + 1.0f) - 1.0f) * 0.5f);
    while ((a + 1) * (a + 2) / 2 <= p) a++;
    while (a * (a + 1) / 2 > p) a--;
    g_pa[p] = a;
    g_pb[p] = p - a * (a + 1) / 2;
}

__global__ void uv_kernel(const float* __restrict__ x, const float* __restrict__ gW0) {
    int n = blockIdx.x / OO;
    int a = blockIdx.x % OO;
    int j = threadIdx.x;
    __shared__ float f[CP];
    if (j < CP) {
        float val;
        if (j < 24)       val = x[((n * 24 + j) * OO) + a];
        else if (j == 24) val = -1.0f + 2.0f * (float)(a / 12) / 11.0f;
        else              val = -1.0f + 2.0f * (float)(a % 12) / 11.0f;
        f[j] = val;
    }
    __syncthreads();
    float u = 0.0f, v = 0.0f;
#pragma unroll
    for (int c = 0; c < CP; c++) {
        float fc = f[c];
        v = fmaf(fc, gW0[c * GT + j], v);
        u = fmaf(fc, gW0[(CP + c) * GT + j], u);
    }
    g_u[(n * OO + a) * GT + j] = u;
    g_v[(n * OO + a) * GT + j] = v;
}

__global__ void base_kernel(const float* __restrict__ q, const float* __restrict__ gW0,
                            const float* __restrict__ gb0) {
    int n = blockIdx.x;
    int j = threadIdx.x;
    float s = gb0[j];
#pragma unroll 8
    for (int k = 0; k < HD; k++)
        s = fmaf(q[n * HD + k], gW0[(2 * CP + k) * GT + j], s);
    g_base[n * GT + j] = s;
}

__global__ void prepB_kernel(const float* __restrict__ gW1, const float* __restrict__ gW2,
                             const float* __restrict__ gW3) {
    int l = blockIdx.y;
    int nrow = blockIdx.x;
    int k = threadIdx.x;
    const float* W = (l == 0) ? gW1 : (l == 1) ? gW2 : gW3;
    float w = W[k * GT + nrow];
    __nv_bfloat16 h = __float2bfloat16(w);
    float r = w - __bfloat162float(h);
    g_Bh[(l * GT + nrow) * GT + k] = h;
    g_Bl[(l * GT + nrow) * GT + k] = __float2bfloat16(r);
}

// ---------------- main HMMA kernel ----------------
__global__ void __launch_bounds__(256, 1) rn_main(
    const float* __restrict__ gb1, const float* __restrict__ gb2,
    const float* __restrict__ gb3)
{
    extern __shared__ char smem[];
    const uint32_t sb = smem_u32(smem);
    const int tid  = threadIdx.x;
    const int lane = tid & 31;
    const int wid  = tid >> 5;
    const int wm   = wid >> 2;      // 0..1  (m half)
    const int wn   = wid & 3;       // 0..3  (n quarter)
    const int tile = blockIdx.x;
    const int n    = blockIdx.y;
    const int pbase = tile * TM;

    __nv_bfloat16* sAh = (__nv_bfloat16*)(smem + SM_AH);
    __nv_bfloat16* sAl = (__nv_bfloat16*)(smem + SM_AL);
    float* spart = (float*)(smem + SM_PART);

    // ---- layer-0 activation build: A[row][k] = relu(u + v + base) ----
    {
        int row = tid & 127;
        int kh  = (tid >> 7) * 128;
        int p = pbase + row;
        const float* up = g_u + (n * OO + g_pa[p]) * GT + kh;
        const float* vp = g_v + (n * OO + g_pb[p]) * GT + kh;
        const float* bp = g_base + n * GT + kh;
        uint32_t* ah = (uint32_t*)(sAh + row * ASTR + kh);
        uint32_t* al = (uint32_t*)(sAl + row * ASTR + kh);
#pragma unroll 8
        for (int k = 0; k < 128; k += 2) {
            float2 uu = *(const float2*)(up + k);
            float2 vv = *(const float2*)(vp + k);
            float2 bb = *(const float2*)(bp + k);
            float f0 = fmaxf(uu.x + vv.x + bb.x, 0.0f);
            float f1 = fmaxf(uu.y + vv.y + bb.y, 0.0f);
            __nv_bfloat16 h0 = __float2bfloat16(f0), h1 = __float2bfloat16(f1);
            float r0 = f0 - __bfloat162float(h0);
            float r1 = f1 - __bfloat162float(h1);
            ah[k >> 1] = pack2(h0, h1);
            al[k >> 1] = pack2(__float2bfloat16(r0), __float2bfloat16(r1));
        }
    }

    float acc[4][8][4];

    // ldmatrix per-lane addressing
    const uint32_t aRow  = (uint32_t)(wm * 64 + (lane & 15));
    const uint32_t aKoff = (uint32_t)((lane >> 4) * 16);           // byte
    const uint32_t bRow  = (uint32_t)(((lane >> 4) & 1) * 8 + (lane & 7));
    const uint32_t bKoff = (uint32_t)(((lane >> 3) & 1) * 16);     // byte

    for (int layer = 0; layer < 3; layer++) {
        const __nv_bfloat16* Bh = g_Bh + layer * GT * GT;
        const __nv_bfloat16* Bl = g_Bl + layer * GT * GT;
        const float* gb = (layer == 0) ? gb1 : (layer == 1) ? gb2 : gb3;

#pragma unroll
        for (int mt = 0; mt < 4; mt++)
#pragma unroll
            for (int n8 = 0; n8 < 8; n8++)
#pragma unroll
                for (int r = 0; r < 4; r++) acc[mt][n8][r] = 0.0f;

        // chunk loader: 256 rows x 32 k (64B) for hi and lo
        auto load_chunk = [&](int kc) {
            uint32_t dbase = sb + SM_B + (uint32_t)((kc & 1) * BBUF);
#pragma unroll
            for (int i = 0; i < 4; i++) {
                int v = tid + i * 256;
                int row = v >> 2, seg = v & 3;
                uint32_t d = dbase + (uint32_t)(row * BSTR + seg * 16);
                cpa16(d,         Bh + row * GT + kc * 32 + seg * 8);
                cpa16(d + BTERM, Bl + row * GT + kc * 32 + seg * 8);
            }
            CP_COMMIT();
        };

        load_chunk(0);
        load_chunk(1);

        for (int kc = 0; kc < 8; kc++) {
            if (kc < 7) { asm volatile("cp.async.wait_group 1;" ::: "memory"); }
            else        { asm volatile("cp.async.wait_group 0;" ::: "memory"); }
            __syncthreads();

            uint32_t bbase = sb + SM_B + (uint32_t)((kc & 1) * BBUF);
#pragma unroll
            for (int s = 0; s < 2; s++) {
                uint32_t ah[4][4], al[4][4], bh[8][2], bl[8][2];
                uint32_t kb = (uint32_t)(kc * 64 + s * 32) + aKoff;

                // B hi frags
#pragma unroll
                for (int ntp = 0; ntp < 4; ntp++) {
                    uint32_t addr = bbase + (uint32_t)((wn * 64 + ntp * 16) + bRow) * BSTR
                                  + (uint32_t)(s * 32) + bKoff;
                    ldsm4(bh[2*ntp][0], bh[2*ntp][1], bh[2*ntp+1][0], bh[2*ntp+1][1], addr);
                }
                // A hi frags
#pragma unroll
                for (int mt = 0; mt < 4; mt++) {
                    uint32_t addr = sb + SM_AH + ((aRow + (uint32_t)(mt * 16)) * ASTR) * 2 + kb;
                    ldsm4(ah[mt][0], ah[mt][1], ah[mt][2], ah[mt][3], addr);
                }
                // term 1: Ah * Bh
#pragma unroll
                for (int mt = 0; mt < 4; mt++)
#pragma unroll
                    for (int n8 = 0; n8 < 8; n8++) mma16816(acc[mt][n8], ah[mt], bh[n8]);
                // B lo frags + term 3: Ah * Bl
#pragma unroll
                for (int ntp = 0; ntp < 4; ntp++) {
                    uint32_t addr = bbase + (uint32_t)((wn * 64 + ntp * 16) + bRow) * BSTR
                                  + (uint32_t)(s * 32) + bKoff + BTERM;
                    ldsm4(bl[2*ntp][0], bl[2*ntp][1], bl[2*ntp+1][0], bl[2*ntp+1][1], addr);
                }
#pragma unroll
                for (int mt = 0; mt < 4; mt++)
#pragma unroll
                    for (int n8 = 0; n8 < 8; n8++) mma16816(acc[mt][n8], ah[mt], bl[n8]);
                // A lo frags + term 2: Al * Bh
#pragma unroll
                for (int mt = 0; mt < 4; mt++) {
                    uint32_t addr = sb + SM_AH + ((aRow + (uint32_t)(mt * 16)) * ASTR) * 2 + kb
                                  + SM_AL;
                    ldsm4(al[mt][0], al[mt][1], al[mt][2], al[mt][3], addr);
                }
#pragma unroll
                for (int mt = 0; mt < 4; mt++)
#pragma unroll
                    for (int n8 = 0; n8 < 8; n8++) mma16816(acc[mt][n8], al[mt], bh[n8]);
            }
            __syncthreads();
            if (kc + 2 < 8) load_chunk(kc + 2);
        }

        if (layer < 2) {
            // epilogue: relu(D + bias) -> hi/lo bf16 -> back into sA
#pragma unroll
            for (int n8 = 0; n8 < 8; n8++) {
                int c0 = wn * 64 + n8 * 8 + 2 * (lane & 3);
                float b0 = gb[c0], b1 = gb[c0 + 1];
#pragma unroll
                for (int mt = 0; mt < 4; mt++) {
                    int r0 = wm * 64 + mt * 16 + (lane >> 2);
                    float f00 = fmaxf(acc[mt][n8][0] + b0, 0.0f);
                    float f01 = fmaxf(acc[mt][n8][1] + b1, 0.0f);
                    float f10 = fmaxf(acc[mt][n8][2] + b0, 0.0f);
                    float f11 = fmaxf(acc[mt][n8][3] + b1, 0.0f);
                    __nv_bfloat16 h00 = __float2bfloat16(f00), h01 = __float2bfloat16(f01);
                    __nv_bfloat16 h10 = __float2bfloat16(f10), h11 = __float2bfloat16(f11);
                    *(uint32_t*)(sAh + r0 * ASTR + c0)       = pack2(h00, h01);
                    *(uint32_t*)(sAh + (r0 + 8) * ASTR + c0) = pack2(h10, h11);
                    *(uint32_t*)(sAl + r0 * ASTR + c0)       =
                        pack2(__float2bfloat16(f00 - __bfloat162float(h00)),
                              __float2bfloat16(f01 - __bfloat162float(h01)));
                    *(uint32_t*)(sAl + (r0 + 8) * ASTR + c0) =
                        pack2(__float2bfloat16(f10 - __bfloat162float(h10)),
                              __float2bfloat16(f11 - __bfloat162float(h11)));
                }
            }
            // visibility guaranteed by the __syncthreads after kc=0's wait next layer
        } else {
            // final layer: relu+bias, mask rows >= NPAIR, column-sum over 128 rows
#pragma unroll
            for (int n8 = 0; n8 < 8; n8++) {
                int c0 = wn * 64 + n8 * 8 + 2 * (lane & 3);
                float b0 = gb[c0], b1 = gb[c0 + 1];
                float s0 = 0.0f, s1 = 0.0f;
#pragma unroll
                for (int mt = 0; mt < 4; mt++) {
                    int gr = pbase + wm * 64 + mt * 16 + (lane >> 2);
                    if (gr < NPAIR) {
                        s0 += fmaxf(acc[mt][n8][0] + b0, 0.0f);
                        s1 += fmaxf(acc[mt][n8][1] + b1, 0.0f);
                    }
                    if (gr + 8 < NPAIR) {
                        s0 += fmaxf(acc[mt][n8][2] + b0, 0.0f);
                        s1 += fmaxf(acc[mt][n8][3] + b1, 0.0f);
                    }
                }
                s0 += __shfl_xor_sync(0xFFFFFFFFu, s0, 4);
                s0 += __shfl_xor_sync(0xFFFFFFFFu, s0, 8);
                s0 += __shfl_xor_sync(0xFFFFFFFFu, s0, 16);
                s1 += __shfl_xor_sync(0xFFFFFFFFu, s1, 4);
                s1 += __shfl_xor_sync(0xFFFFFFFFu, s1, 8);
                s1 += __shfl_xor_sync(0xFFFFFFFFu, s1, 16);
                if (lane < 4) {
                    spart[wm * 256 + c0]     = s0;
                    spart[wm * 256 + c0 + 1] = s1;
                }
            }
            __syncthreads();
            {
                float s = spart[tid] + spart[256 + tid];
                g_partial[(n * NTILE + tile) * GT + tid] = s;
            }
        }
    }
}

// ---------------- reduce partials + f_phi ----------------
__global__ void fphi_kernel(const float* __restrict__ fW0, const float* __restrict__ fb0,
                            const float* __restrict__ fW1, const float* __restrict__ fb1,
                            const float* __restrict__ fW2, const float* __restrict__ fb2,
                            float* __restrict__ out)
{
    int n = blockIdx.x;
    int j = threadIdx.x;
    __shared__ float rs[GT];
    __shared__ float y1[GT];
    __shared__ float y2[GT];

    float s = 0.0f;
    for (int t = 0; t < NTILE; t++)
        s += g_partial[(n * NTILE + t) * GT + j];
    rs[j] = s;
    __syncthreads();

    float h = fb0[j];
#pragma unroll 8
    for (int k = 0; k < GT; k++) h = fmaf(rs[k], fW0[k * GT + j], h);
    y1[j] = fmaxf(h, 0.0f);
    __syncthreads();

    h = fb1[j];
#pragma unroll 8
    for (int k = 0; k < GT; k++) h = fmaf(y1[k], fW1[k * GT + j], h);
    y2[j] = fmaxf(h, 0.0f);
    __syncthreads();

    if (j < AOUT) {
        float o = fb2[j];
#pragma unroll 8
        for (int k = 0; k < GT; k++) o = fmaf(y2[k], fW2[k * AOUT + j], o);
        out[n * AOUT + j] = o;
    }
}

extern "C" void kernel_launch(void* const* d_in, const int* in_sizes, int n_in,
                              void* d_out, int out_size)
{
    const float* x   = (const float*)d_in[0];
    const float* q   = (const float*)d_in[1];
    const float* gW0 = (const float*)d_in[2];
    const float* gb0 = (const float*)d_in[3];
    const float* gW1 = (const float*)d_in[4];
    const float* gb1 = (const float*)d_in[5];
    const float* gW2 = (const float*)d_in[6];
    const float* gb2 = (const float*)d_in[7];
    const float* gW3 = (const float*)d_in[8];
    const float* gb3 = (const float*)d_in[9];
    const float* fW0 = (const float*)d_in[10];
    const float* fb0 = (const float*)d_in[11];
    const float* fW1 = (const float*)d_in[12];
    const float* fb1 = (const float*)d_in[13];
    const float* fW2 = (const float*)d_in[14];
    const float* fb2 = (const float*)d_in[15];
    float* out = (float*)d_out;

    cudaFuncSetAttribute(rn_main, cudaFuncAttributeMaxDynamicSharedMemorySize, SMTOT);

    pairs_kernel<<<(PADP + 255) / 256, 256>>>();
    uv_kernel<<<BN * OO, 256>>>(x, gW0);
    base_kernel<<<BN, 256>>>(q, gW0, gb0);
    prepB_kernel<<<dim3(GT, 3), GT>>>(gW1, gW2, gW3);
    rn_main<<<dim3(NTILE, BN), 256, SMTOT>>>(gb1, gb2, gb3);
    fphi_kernel<<<BN, 256>>>(fW0, fb0, fW1, fb1, fW2, fb2, out);
}

// round 15
// speedup vs baseline: 1.0007x; 1.0007x over previous
#include <cuda_runtime.h>
#include <cuda_bf16.h>
#include <cstdint>

// ---------------- problem constants ----------------
#define BN    32
#define OO    144
#define CP    26
#define GT    256
#define HD    128
#define AOUT  28
#define NPAIR 10440
#define TM    128            // pairs per CTA tile
#define NTILE 82             // ceil(10440/128)
#define PADP  (NTILE*TM)     // 10496

// smem layout (bytes)
#define ASTR  264            // bf16 elems per A row (256 + 8 pad -> +16B skew)
#define BSTR  80             // bytes per B row (64B data + 16B pad)
#define SM_AH 0
#define SM_AL (128*ASTR*2)            // 67584
#define SM_B  (2*128*ASTR*2)          // 135168
#define BTERM (256*BSTR)              // 20480 (one term, one buffer)
#define BBUF  (2*BTERM)               // 40960 (hi+lo)
#define SM_PART (SM_B + 2*BBUF)       // 217088
#define SMTOT   (SM_PART + 2048)      // 219136

typedef unsigned long long u64;

// ---------------- device scratch ----------------
__device__ float g_u[BN*OO*GT];
__device__ float g_v[BN*OO*GT];
__device__ float g_base[BN*GT];
__device__ int   g_pa[PADP];
__device__ int   g_pb[PADP];
__device__ float g_partial[BN*NTILE*GT];
__device__ __nv_bfloat16 g_Bh[3*GT*GT];   // W^T hi, [l][n][k] (K-major)
__device__ __nv_bfloat16 g_Bl[3*GT*GT];   // W^T lo

// ---------------- helpers ----------------
__device__ __forceinline__ uint32_t smem_u32(const void* p) {
    uint32_t a;
    asm("{ .reg .u64 t; cvta.to.shared.u64 t, %1; cvt.u32.u64 %0, t; }" : "=r"(a) : "l"(p));
    return a;
}
__device__ __forceinline__ uint32_t pack2(__nv_bfloat16 a, __nv_bfloat16 b) {
    return (uint32_t)__bfloat16_as_ushort(a) | ((uint32_t)__bfloat16_as_ushort(b) << 16);
}
__device__ __forceinline__ void ldsm4(uint32_t& r0, uint32_t& r1, uint32_t& r2, uint32_t& r3,
                                      uint32_t addr) {
    asm volatile("ldmatrix.sync.aligned.m8n8.x4.shared.b16 {%0,%1,%2,%3}, [%4];"
        : "=r"(r0), "=r"(r1), "=r"(r2), "=r"(r3) : "r"(addr));
}
__device__ __forceinline__ void mma16816(float* d, const uint32_t* a, const uint32_t* b) {
    asm volatile("mma.sync.aligned.m16n8k16.row.col.f32.bf16.bf16.f32 "
        "{%0,%1,%2,%3}, {%4,%5,%6,%7}, {%8,%9}, {%0,%1,%2,%3};"
        : "+f"(d[0]), "+f"(d[1]), "+f"(d[2]), "+f"(d[3])
        : "r"(a[0]), "r"(a[1]), "r"(a[2]), "r"(a[3]), "r"(b[0]), "r"(b[1]));
}
__device__ __forceinline__ void cpa16(uint32_t dst, const void* src) {
    asm volatile("cp.async.cg.shared.global [%0], [%1], 16;" :: "r"(dst), "l"(src));
}
#define CP_COMMIT() asm volatile("cp.async.commit_group;" ::: "memory")

// ---------------- prep kernels ----------------
__global__ void pairs_kernel() {
    int p = blockIdx.x * blockDim.x + threadIdx.x;
    if (p >= PADP) return;
    if (p >= NPAIR) { g_pa[p] = 0; g_pb[p] = 0; return; }
    int a = (int)((sqrtf(8.0f * (float)p + 1.0f) - 1.0f) * 0.5f);
    while ((a + 1) * (a + 2) / 2 <= p) a++;
    while (a * (a + 1) / 2 > p) a--;
    g_pa[p] = a;
    g_pb[p] = p - a * (a + 1) / 2;
}

__global__ void uv_kernel(const float* __restrict__ x, const float* __restrict__ gW0) {
    int n = blockIdx.x / OO;
    int a = blockIdx.x % OO;
    int j = threadIdx.x;
    __shared__ float f[CP];
    if (j < CP) {
        float val;
        if (j < 24)       val = x[((n * 24 + j) * OO) + a];
        else if (j == 24) val = -1.0f + 2.0f * (float)(a / 12) / 11.0f;
        else              val = -1.0f + 2.0f * (float)(a % 12) / 11.0f;
        f[j] = val;
    }
    __syncthreads();
    float u = 0.0f, v = 0.0f;
#pragma unroll
    for (int c = 0; c < CP; c++) {
        float fc = f[c];
        v = fmaf(fc, gW0[c * GT + j], v);
        u = fmaf(fc, gW0[(CP + c) * GT + j], u);
    }
    g_u[(n * OO + a) * GT + j] = u;
    g_v[(n * OO + a) * GT + j] = v;
}

__global__ void base_kernel(const float* __restrict__ q, const float* __restrict__ gW0,
                            const float* __restrict__ gb0) {
    int n = blockIdx.x;
    int j = threadIdx.x;
    float s = gb0[j];
#pragma unroll 8
    for (int k = 0; k < HD; k++)
        s = fmaf(q[n * HD + k], gW0[(2 * CP + k) * GT + j], s);
    g_base[n * GT + j] = s;
}

__global__ void prepB_kernel(const float* __restrict__ gW1, const float* __restrict__ gW2,
                             const float* __restrict__ gW3) {
    int l = blockIdx.y;
    int nrow = blockIdx.x;
    int k = threadIdx.x;
    const float* W = (l == 0) ? gW1 : (l == 1) ? gW2 : gW3;
    float w = W[k * GT + nrow];
    __nv_bfloat16 h = __float2bfloat16(w);
    float r = w - __bfloat162float(h);
    g_Bh[(l * GT + nrow) * GT + k] = h;
    g_Bl[(l * GT + nrow) * GT + k] = __float2bfloat16(r);
}

// ---------------- main HMMA kernel ----------------
__global__ void __launch_bounds__(256, 1) rn_main(
    const float* __restrict__ gb1, const float* __restrict__ gb2,
    const float* __restrict__ gb3)
{
    extern __shared__ char smem[];
    const uint32_t sb = smem_u32(smem);
    const int tid  = threadIdx.x;
    const int lane = tid & 31;
    const int wid  = tid >> 5;
    const int wm   = wid >> 2;      // 0..1  (m half)
    const int wn   = wid & 3;       // 0..3  (n quarter)
    const int tile = blockIdx.x;
    const int n    = blockIdx.y;
    const int pbase = tile * TM;

    __nv_bfloat16* sAh = (__nv_bfloat16*)(smem + SM_AH);
    __nv_bfloat16* sAl = (__nv_bfloat16*)(smem + SM_AL);
    float* spart = (float*)(smem + SM_PART);

    // ---- layer-0 activation build: A[row][k] = relu(u + v + base) ----
    {
        int row = tid & 127;
        int kh  = (tid >> 7) * 128;
        int p = pbase + row;
        const float* up = g_u + (n * OO + g_pa[p]) * GT + kh;
        const float* vp = g_v + (n * OO + g_pb[p]) * GT + kh;
        const float* bp = g_base + n * GT + kh;
        uint32_t* ah = (uint32_t*)(sAh + row * ASTR + kh);
        uint32_t* al = (uint32_t*)(sAl + row * ASTR + kh);
#pragma unroll 8
        for (int k = 0; k < 128; k += 2) {
            float2 uu = *(const float2*)(up + k);
            float2 vv = *(const float2*)(vp + k);
            float2 bb = *(const float2*)(bp + k);
            float f0 = fmaxf(uu.x + vv.x + bb.x, 0.0f);
            float f1 = fmaxf(uu.y + vv.y + bb.y, 0.0f);
            __nv_bfloat16 h0 = __float2bfloat16(f0), h1 = __float2bfloat16(f1);
            float r0 = f0 - __bfloat162float(h0);
            float r1 = f1 - __bfloat162float(h1);
            ah[k >> 1] = pack2(h0, h1);
            al[k >> 1] = pack2(__float2bfloat16(r0), __float2bfloat16(r1));
        }
    }

    float acc[4][8][4];

    // ldmatrix per-lane addressing
    const uint32_t aRow  = (uint32_t)(wm * 64 + (lane & 15));
    const uint32_t aKoff = (uint32_t)((lane >> 4) * 16);           // byte
    const uint32_t bRow  = (uint32_t)(((lane >> 4) & 1) * 8 + (lane & 7));
    const uint32_t bKoff = (uint32_t)(((lane >> 3) & 1) * 16);     // byte

    for (int layer = 0; layer < 3; layer++) {
        const __nv_bfloat16* Bh = g_Bh + layer * GT * GT;
        const __nv_bfloat16* Bl = g_Bl + layer * GT * GT;
        const float* gb = (layer == 0) ? gb1 : (layer == 1) ? gb2 : gb3;

#pragma unroll
        for (int mt = 0; mt < 4; mt++)
#pragma unroll
            for (int n8 = 0; n8 < 8; n8++)
#pragma unroll
                for (int r = 0; r < 4; r++) acc[mt][n8][r] = 0.0f;

        // chunk loader: 256 rows x 32 k (64B) for hi and lo
        auto load_chunk = [&](int kc) {
            uint32_t dbase = sb + SM_B + (uint32_t)((kc & 1) * BBUF);
#pragma unroll
            for (int i = 0; i < 4; i++) {
                int v = tid + i * 256;
                int row = v >> 2, seg = v & 3;
                uint32_t d = dbase + (uint32_t)(row * BSTR + seg * 16);
                cpa16(d,         Bh + row * GT + kc * 32 + seg * 8);
                cpa16(d + BTERM, Bl + row * GT + kc * 32 + seg * 8);
            }
            CP_COMMIT();
        };

        load_chunk(0);
        load_chunk(1);

        for (int kc = 0; kc < 8; kc++) {
            if (kc < 7) { asm volatile("cp.async.wait_group 1;" ::: "memory"); }
            else        { asm volatile("cp.async.wait_group 0;" ::: "memory"); }
            __syncthreads();

            uint32_t bbase = sb + SM_B + (uint32_t)((kc & 1) * BBUF);
#pragma unroll
            for (int s = 0; s < 2; s++) {
                uint32_t ah[4][4], al[4][4], bh[8][2], bl[8][2];
                uint32_t kb = (uint32_t)(kc * 64 + s * 32) + aKoff;

                // B hi frags
#pragma unroll
                for (int ntp = 0; ntp < 4; ntp++) {
                    uint32_t addr = bbase + (uint32_t)((wn * 64 + ntp * 16) + bRow) * BSTR
                                  + (uint32_t)(s * 32) + bKoff;
                    ldsm4(bh[2*ntp][0], bh[2*ntp][1], bh[2*ntp+1][0], bh[2*ntp+1][1], addr);
                }
                // A hi frags
#pragma unroll
                for (int mt = 0; mt < 4; mt++) {
                    uint32_t addr = sb + SM_AH + ((aRow + (uint32_t)(mt * 16)) * ASTR) * 2 + kb;
                    ldsm4(ah[mt][0], ah[mt][1], ah[mt][2], ah[mt][3], addr);
                }
                // term 1: Ah * Bh
#pragma unroll
                for (int mt = 0; mt < 4; mt++)
#pragma unroll
                    for (int n8 = 0; n8 < 8; n8++) mma16816(acc[mt][n8], ah[mt], bh[n8]);
                // B lo frags + term 3: Ah * Bl
#pragma unroll
                for (int ntp = 0; ntp < 4; ntp++) {
                    uint32_t addr = bbase + (uint32_t)((wn * 64 + ntp * 16) + bRow) * BSTR
                                  + (uint32_t)(s * 32) + bKoff + BTERM;
                    ldsm4(bl[2*ntp][0], bl[2*ntp][1], bl[2*ntp+1][0], bl[2*ntp+1][1], addr);
                }
#pragma unroll
                for (int mt = 0; mt < 4; mt++)
#pragma unroll
                    for (int n8 = 0; n8 < 8; n8++) mma16816(acc[mt][n8], ah[mt], bl[n8]);
                // A lo frags + term 2: Al * Bh
#pragma unroll
                for (int mt = 0; mt < 4; mt++) {
                    uint32_t addr = sb + SM_AH + ((aRow + (uint32_t)(mt * 16)) * ASTR) * 2 + kb
                                  + SM_AL;
                    ldsm4(al[mt][0], al[mt][1], al[mt][2], al[mt][3], addr);
                }
#pragma unroll
                for (int mt = 0; mt < 4; mt++)
#pragma unroll
                    for (int n8 = 0; n8 < 8; n8++) mma16816(acc[mt][n8], al[mt], bh[n8]);
            }
            __syncthreads();
            if (kc + 2 < 8) load_chunk(kc + 2);
        }

        if (layer < 2) {
            // epilogue: relu(D + bias) -> hi/lo bf16 -> back into sA
#pragma unroll
            for (int n8 = 0; n8 < 8; n8++) {
                int c0 = wn * 64 + n8 * 8 + 2 * (lane & 3);
                float b0 = gb[c0], b1 = gb[c0 + 1];
#pragma unroll
                for (int mt = 0; mt < 4; mt++) {
                    int r0 = wm * 64 + mt * 16 + (lane >> 2);
                    float f00 = fmaxf(acc[mt][n8][0] + b0, 0.0f);
                    float f01 = fmaxf(acc[mt][n8][1] + b1, 0.0f);
                    float f10 = fmaxf(acc[mt][n8][2] + b0, 0.0f);
                    float f11 = fmaxf(acc[mt][n8][3] + b1, 0.0f);
                    __nv_bfloat16 h00 = __float2bfloat16(f00), h01 = __float2bfloat16(f01);
                    __nv_bfloat16 h10 = __float2bfloat16(f10), h11 = __float2bfloat16(f11);
                    *(uint32_t*)(sAh + r0 * ASTR + c0)       = pack2(h00, h01);
                    *(uint32_t*)(sAh + (r0 + 8) * ASTR + c0) = pack2(h10, h11);
                    *(uint32_t*)(sAl + r0 * ASTR + c0)       =
                        pack2(__float2bfloat16(f00 - __bfloat162float(h00)),
                              __float2bfloat16(f01 - __bfloat162float(h01)));
                    *(uint32_t*)(sAl + (r0 + 8) * ASTR + c0) =
                        pack2(__float2bfloat16(f10 - __bfloat162float(h10)),
                              __float2bfloat16(f11 - __bfloat162float(h11)));
                }
            }
            // visibility guaranteed by the __syncthreads after kc=0's wait next layer
        } else {
            // final layer: relu+bias, mask rows >= NPAIR, column-sum over 128 rows
#pragma unroll
            for (int n8 = 0; n8 < 8; n8++) {
                int c0 = wn * 64 + n8 * 8 + 2 * (lane & 3);
                float b0 = gb[c0], b1 = gb[c0 + 1];
                float s0 = 0.0f, s1 = 0.0f;
#pragma unroll
                for (int mt = 0; mt < 4; mt++) {
                    int gr = pbase + wm * 64 + mt * 16 + (lane >> 2);
                    if (gr < NPAIR) {
                        s0 += fmaxf(acc[mt][n8][0] + b0, 0.0f);
                        s1 += fmaxf(acc[mt][n8][1] + b1, 0.0f);
                    }
                    if (gr + 8 < NPAIR) {
                        s0 += fmaxf(acc[mt][n8][2] + b0, 0.0f);
                        s1 += fmaxf(acc[mt][n8][3] + b1, 0.0f);
                    }
                }
                s0 += __shfl_xor_sync(0xFFFFFFFFu, s0, 4);
                s0 += __shfl_xor_sync(0xFFFFFFFFu, s0, 8);
                s0 += __shfl_xor_sync(0xFFFFFFFFu, s0, 16);
                s1 += __shfl_xor_sync(0xFFFFFFFFu, s1, 4);
                s1 += __shfl_xor_sync(0xFFFFFFFFu, s1, 8);
                s1 += __shfl_xor_sync(0xFFFFFFFFu, s1, 16);
                if (lane < 4) {
                    spart[wm * 256 + c0]     = s0;
                    spart[wm * 256 + c0 + 1] = s1;
                }
            }
            __syncthreads();
            {
                float s = spart[tid] + spart[256 + tid];
                g_partial[(n * NTILE + tile) * GT + tid] = s;
            }
        }
    }
}

// ---------------- reduce partials + f_phi ----------------
__global__ void fphi_kernel(const float* __restrict__ fW0, const float* __restrict__ fb0,
                            const float* __restrict__ fW1, const float* __restrict__ fb1,
                            const float* __restrict__ fW2, const float* __restrict__ fb2,
                            float* __restrict__ out)
{
    int n = blockIdx.x;
    int j = threadIdx.x;
    __shared__ float rs[GT];
    __shared__ float y1[GT];
    __shared__ float y2[GT];

    float s = 0.0f;
    for (int t = 0; t < NTILE; t++)
        s += g_partial[(n * NTILE + t) * GT + j];
    rs[j] = s;
    __syncthreads();

    float h = fb0[j];
#pragma unroll 8
    for (int k = 0; k < GT; k++) h = fmaf(rs[k], fW0[k * GT + j], h);
    y1[j] = fmaxf(h, 0.0f);
    __syncthreads();

    h = fb1[j];
#pragma unroll 8
    for (int k = 0; k < GT; k++) h = fmaf(y1[k], fW1[k * GT + j], h);
    y2[j] = fmaxf(h, 0.0f);
    __syncthreads();

    if (j < AOUT) {
        float o = fb2[j];
#pragma unroll 8
        for (int k = 0; k < GT; k++) o = fmaf(y2[k], fW2[k * AOUT + j], o);
        out[n * AOUT + j] = o;
    }
}

extern "C" void kernel_launch(void* const* d_in, const int* in_sizes, int n_in,
                              void* d_out, int out_size)
{
    const float* x   = (const float*)d_in[0];
    const float* q   = (const float*)d_in[1];
    const float* gW0 = (const float*)d_in[2];
    const float* gb0 = (const float*)d_in[3];
    const float* gW1 = (const float*)d_in[4];
    const float* gb1 = (const float*)d_in[5];
    const float* gW2 = (const float*)d_in[6];
    const float* gb2 = (const float*)d_in[7];
    const float* gW3 = (const float*)d_in[8];
    const float* gb3 = (const float*)d_in[9];
    const float* fW0 = (const float*)d_in[10];
    const float* fb0 = (const float*)d_in[11];
    const float* fW1 = (const float*)d_in[12];
    const float* fb1 = (const float*)d_in[13];
    const float* fW2 = (const float*)d_in[14];
    const float* fb2 = (const float*)d_in[15];
    float* out = (float*)d_out;

    cudaFuncSetAttribute(rn_main, cudaFuncAttributeMaxDynamicSharedMemorySize, SMTOT);

    pairs_kernel<<<(PADP + 255) / 256, 256>>>();
    uv_kernel<<<BN * OO, 256>>>(x, gW0);
    base_kernel<<<BN, 256>>>(q, gW0, gb0);
    prepB_kernel<<<dim3(GT, 3), GT>>>(gW1, gW2, gW3);
    rn_main<<<dim3(NTILE, BN), 256, SMTOT>>>(gb1, gb2, gb3);
    fphi_kernel<<<BN, 256>>>(fW0, fb0, fW1, fb1, fW2, fb2, out);
}

// round 16
// speedup vs baseline: 1.0014x; 1.0007x over previous
#include <cuda_runtime.h>
#include <cuda_bf16.h>
#include <cstdint>

// ---------------- problem constants ----------------
#define BN    32
#define OO    144
#define CP    26
#define GT    256
#define HD    128
#define AOUT  28
#define NPAIR 10440
#define TM    128            // pairs per CTA tile
#define NTILE 82             // ceil(10440/128)
#define PADP  (NTILE*TM)     // 10496

// smem layout (bytes)
#define ASTR  264            // bf16 elems per A row (256 + 8 pad -> +16B skew)
#define BSTR  80             // bytes per B row (64B data + 16B pad)
#define SM_AH 0
#define SM_AL (128*ASTR*2)            // 67584
#define SM_B  (2*128*ASTR*2)          // 135168
#define BTERM (256*BSTR)              // 20480 (one term, one buffer)
#define BBUF  (2*BTERM)               // 40960 (hi+lo)
#define SM_PART (SM_B + 2*BBUF)       // 217088
#define SMTOT   (SM_PART + 2048)      // 219136

typedef unsigned long long u64;

// ---------------- device scratch ----------------
__device__ float g_u[BN*OO*GT];
__device__ float g_v[BN*OO*GT];
__device__ float g_base[BN*GT];
__device__ int   g_pa[PADP];
__device__ int   g_pb[PADP];
__device__ float g_partial[BN*NTILE*GT];
__device__ __nv_bfloat16 g_Bh[3*GT*GT];   // W^T hi, [l][n][k] (K-major)
__device__ __nv_bfloat16 g_Bl[3*GT*GT];   // W^T lo

// ---------------- helpers ----------------
__device__ __forceinline__ uint32_t smem_u32(const void* p) {
    uint32_t a;
    asm("{ .reg .u64 t; cvta.to.shared.u64 t, %1; cvt.u32.u64 %0, t; }" : "=r"(a) : "l"(p));
    return a;
}
__device__ __forceinline__ uint32_t pack2(__nv_bfloat16 a, __nv_bfloat16 b) {
    return (uint32_t)__bfloat16_as_ushort(a) | ((uint32_t)__bfloat16_as_ushort(b) << 16);
}
__device__ __forceinline__ void ldsm4(uint32_t& r0, uint32_t& r1, uint32_t& r2, uint32_t& r3,
                                      uint32_t addr) {
    asm volatile("ldmatrix.sync.aligned.m8n8.x4.shared.b16 {%0,%1,%2,%3}, [%4];"
        : "=r"(r0), "=r"(r1), "=r"(r2), "=r"(r3) : "r"(addr));
}
__device__ __forceinline__ void mma16816(float* d, const uint32_t* a, const uint32_t* b) {
    asm volatile("mma.sync.aligned.m16n8k16.row.col.f32.bf16.bf16.f32 "
        "{%0,%1,%2,%3}, {%4,%5,%6,%7}, {%8,%9}, {%0,%1,%2,%3};"
        : "+f"(d[0]), "+f"(d[1]), "+f"(d[2]), "+f"(d[3])
        : "r"(a[0]), "r"(a[1]), "r"(a[2]), "r"(a[3]), "r"(b[0]), "r"(b[1]));
}
__device__ __forceinline__ void cpa16(uint32_t dst, const void* src) {
    asm volatile("cp.async.cg.shared.global [%0], [%1], 16;" :: "r"(dst), "l"(src));
}
#define CP_COMMIT() asm volatile("cp.async.commit_group;" ::: "memory")

// ---------------- prep kernels ----------------
__global__ void pairs_kernel() {
    int p = blockIdx.x * blockDim.x + threadIdx.x;
    if (p >= PADP) return;
    if (p >= NPAIR) { g_pa[p] = 0; g_pb[p] = 0; return; }
    int a = (int)((sqrtf(8.0f * (float)p + 1.0f) - 1.0f) * 0.5f);
    while ((a + 1) * (a + 2) / 2 <= p) a++;
    while (a * (a + 1) / 2 > p) a--;
    g_pa[p] = a;
    g_pb[p] = p - a * (a + 1) / 2;
}

__global__ void uv_kernel(const float* __restrict__ x, const float* __restrict__ gW0) {
    int n = blockIdx.x / OO;
    int a = blockIdx.x % OO;
    int j = threadIdx.x;
    __shared__ float f[CP];
    if (j < CP) {
        float val;
        if (j < 24)       val = x[((n * 24 + j) * OO) + a];
        else if (j == 24) val = -1.0f + 2.0f * (float)(a / 12) / 11.0f;
        else              val = -1.0f + 2.0f * (float)(a % 12) / 11.0f;
        f[j] = val;
    }
    __syncthreads();
    float u = 0.0f, v = 0.0f;
#pragma unroll
    for (int c = 0; c < CP; c++) {
        float fc = f[c];
        v = fmaf(fc, gW0[c * GT + j], v);
        u = fmaf(fc, gW0[(CP + c) * GT + j], u);
    }
    g_u[(n * OO + a) * GT + j] = u;
    g_v[(n * OO + a) * GT + j] = v;
}

__global__ void base_kernel(const float* __restrict__ q, const float* __restrict__ gW0,
                            const float* __restrict__ gb0) {
    int n = blockIdx.x;
    int j = threadIdx.x;
    float s = gb0[j];
#pragma unroll 8
    for (int k = 0; k < HD; k++)
        s = fmaf(q[n * HD + k], gW0[(2 * CP + k) * GT + j], s);
    g_base[n * GT + j] = s;
}

__global__ void prepB_kernel(const float* __restrict__ gW1, const float* __restrict__ gW2,
                             const float* __restrict__ gW3) {
    int l = blockIdx.y;
    int nrow = blockIdx.x;
    int k = threadIdx.x;
    const float* W = (l == 0) ? gW1 : (l == 1) ? gW2 : gW3;
    float w = W[k * GT + nrow];
    __nv_bfloat16 h = __float2bfloat16(w);
    float r = w - __bfloat162float(h);
    g_Bh[(l * GT + nrow) * GT + k] = h;
    g_Bl[(l * GT + nrow) * GT + k] = __float2bfloat16(r);
}

// ---------------- main HMMA kernel ----------------
__global__ void __launch_bounds__(256, 1) rn_main(
    const float* __restrict__ gb1, const float* __restrict__ gb2,
    const float* __restrict__ gb3)
{
    extern __shared__ char smem[];
    const uint32_t sb = smem_u32(smem);
    const int tid  = threadIdx.x;
    const int lane = tid & 31;
    const int wid  = tid >> 5;
    const int wm   = wid >> 2;      // 0..1  (m half)
    const int wn   = wid & 3;       // 0..3  (n quarter)
    const int tile = blockIdx.x;
    const int n    = blockIdx.y;
    const int pbase = tile * TM;

    __nv_bfloat16* sAh = (__nv_bfloat16*)(smem + SM_AH);
    __nv_bfloat16* sAl = (__nv_bfloat16*)(smem + SM_AL);
    float* spart = (float*)(smem + SM_PART);

    // ---- layer-0 activation build: A[row][k] = relu(u + v + base) ----
    {
        int row = tid & 127;
        int kh  = (tid >> 7) * 128;
        int p = pbase + row;
        const float* up = g_u + (n * OO + g_pa[p]) * GT + kh;
        const float* vp = g_v + (n * OO + g_pb[p]) * GT + kh;
        const float* bp = g_base + n * GT + kh;
        uint32_t* ah = (uint32_t*)(sAh + row * ASTR + kh);
        uint32_t* al = (uint32_t*)(sAl + row * ASTR + kh);
#pragma unroll 8
        for (int k = 0; k < 128; k += 2) {
            float2 uu = *(const float2*)(up + k);
            float2 vv = *(const float2*)(vp + k);
            float2 bb = *(const float2*)(bp + k);
            float f0 = fmaxf(uu.x + vv.x + bb.x, 0.0f);
            float f1 = fmaxf(uu.y + vv.y + bb.y, 0.0f);
            __nv_bfloat16 h0 = __float2bfloat16(f0), h1 = __float2bfloat16(f1);
            float r0 = f0 - __bfloat162float(h0);
            float r1 = f1 - __bfloat162float(h1);
            ah[k >> 1] = pack2(h0, h1);
            al[k >> 1] = pack2(__float2bfloat16(r0), __float2bfloat16(r1));
        }
    }

    float acc[4][8][4];

    // ldmatrix per-lane addressing
    const uint32_t aRow  = (uint32_t)(wm * 64 + (lane & 15));
    const uint32_t aKoff = (uint32_t)((lane >> 4) * 16);           // byte
    const uint32_t bRow  = (uint32_t)(((lane >> 4) & 1) * 8 + (lane & 7));
    const uint32_t bKoff = (uint32_t)(((lane >> 3) & 1) * 16);     // byte

    for (int layer = 0; layer < 3; layer++) {
        const __nv_bfloat16* Bh = g_Bh + layer * GT * GT;
        const __nv_bfloat16* Bl = g_Bl + layer * GT * GT;
        const float* gb = (layer == 0) ? gb1 : (layer == 1) ? gb2 : gb3;

#pragma unroll
        for (int mt = 0; mt < 4; mt++)
#pragma unroll
            for (int n8 = 0; n8 < 8; n8++)
#pragma unroll
                for (int r = 0; r < 4; r++) acc[mt][n8][r] = 0.0f;

        // chunk loader: 256 rows x 32 k (64B) for hi and lo
        auto load_chunk = [&](int kc) {
            uint32_t dbase = sb + SM_B + (uint32_t)((kc & 1) * BBUF);
#pragma unroll
            for (int i = 0; i < 4; i++) {
                int v = tid + i * 256;
                int row = v >> 2, seg = v & 3;
                uint32_t d = dbase + (uint32_t)(row * BSTR + seg * 16);
                cpa16(d,         Bh + row * GT + kc * 32 + seg * 8);
                cpa16(d + BTERM, Bl + row * GT + kc * 32 + seg * 8);
            }
            CP_COMMIT();
        };

        load_chunk(0);
        load_chunk(1);

        for (int kc = 0; kc < 8; kc++) {
            if (kc < 7) { asm volatile("cp.async.wait_group 1;" ::: "memory"); }
            else        { asm volatile("cp.async.wait_group 0;" ::: "memory"); }
            __syncthreads();

            uint32_t bbase = sb + SM_B + (uint32_t)((kc & 1) * BBUF);
#pragma unroll
            for (int s = 0; s < 2; s++) {
                uint32_t ah[4][4], al[4][4], bh[8][2], bl[8][2];
                uint32_t kb = (uint32_t)(kc * 64 + s * 32) + aKoff;

                // B hi frags
#pragma unroll
                for (int ntp = 0; ntp < 4; ntp++) {
                    uint32_t addr = bbase + (uint32_t)((wn * 64 + ntp * 16) + bRow) * BSTR
                                  + (uint32_t)(s * 32) + bKoff;
                    ldsm4(bh[2*ntp][0], bh[2*ntp][1], bh[2*ntp+1][0], bh[2*ntp+1][1], addr);
                }
                // A hi frags
#pragma unroll
                for (int mt = 0; mt < 4; mt++) {
                    uint32_t addr = sb + SM_AH + ((aRow + (uint32_t)(mt * 16)) * ASTR) * 2 + kb;
                    ldsm4(ah[mt][0], ah[mt][1], ah[mt][2], ah[mt][3], addr);
                }
                // term 1: Ah * Bh
#pragma unroll
                for (int mt = 0; mt < 4; mt++)
#pragma unroll
                    for (int n8 = 0; n8 < 8; n8++) mma16816(acc[mt][n8], ah[mt], bh[n8]);
                // B lo frags + term 3: Ah * Bl
#pragma unroll
                for (int ntp = 0; ntp < 4; ntp++) {
                    uint32_t addr = bbase + (uint32_t)((wn * 64 + ntp * 16) + bRow) * BSTR
                                  + (uint32_t)(s * 32) + bKoff + BTERM;
                    ldsm4(bl[2*ntp][0], bl[2*ntp][1], bl[2*ntp+1][0], bl[2*ntp+1][1], addr);
                }
#pragma unroll
                for (int mt = 0; mt < 4; mt++)
#pragma unroll
                    for (int n8 = 0; n8 < 8; n8++) mma16816(acc[mt][n8], ah[mt], bl[n8]);
                // A lo frags + term 2: Al * Bh
#pragma unroll
                for (int mt = 0; mt < 4; mt++) {
                    uint32_t addr = sb + SM_AH + ((aRow + (uint32_t)(mt * 16)) * ASTR) * 2 + kb
                                  + SM_AL;
                    ldsm4(al[mt][0], al[mt][1], al[mt][2], al[mt][3], addr);
                }
#pragma unroll
                for (int mt = 0; mt < 4; mt++)
#pragma unroll
                    for (int n8 = 0; n8 < 8; n8++) mma16816(acc[mt][n8], al[mt], bh[n8]);
            }
            __syncthreads();
            if (kc + 2 < 8) load_chunk(kc + 2);
        }

        if (layer < 2) {
            // epilogue: relu(D + bias) -> hi/lo bf16 -> back into sA
#pragma unroll
            for (int n8 = 0; n8 < 8; n8++) {
                int c0 = wn * 64 + n8 * 8 + 2 * (lane & 3);
                float b0 = gb[c0], b1 = gb[c0 + 1];
#pragma unroll
                for (int mt = 0; mt < 4; mt++) {
                    int r0 = wm * 64 + mt * 16 + (lane >> 2);
                    float f00 = fmaxf(acc[mt][n8][0] + b0, 0.0f);
                    float f01 = fmaxf(acc[mt][n8][1] + b1, 0.0f);
                    float f10 = fmaxf(acc[mt][n8][2] + b0, 0.0f);
                    float f11 = fmaxf(acc[mt][n8][3] + b1, 0.0f);
                    __nv_bfloat16 h00 = __float2bfloat16(f00), h01 = __float2bfloat16(f01);
                    __nv_bfloat16 h10 = __float2bfloat16(f10), h11 = __float2bfloat16(f11);
                    *(uint32_t*)(sAh + r0 * ASTR + c0)       = pack2(h00, h01);
                    *(uint32_t*)(sAh + (r0 + 8) * ASTR + c0) = pack2(h10, h11);
                    *(uint32_t*)(sAl + r0 * ASTR + c0)       =
                        pack2(__float2bfloat16(f00 - __bfloat162float(h00)),
                              __float2bfloat16(f01 - __bfloat162float(h01)));
                    *(uint32_t*)(sAl + (r0 + 8) * ASTR + c0) =
                        pack2(__float2bfloat16(f10 - __bfloat162float(h10)),
                              __float2bfloat16(f11 - __bfloat162float(h11)));
                }
            }
            // visibility guaranteed by the __syncthreads after kc=0's wait next layer
        } else {
            // final layer: relu+bias, mask rows >= NPAIR, column-sum over 128 rows
#pragma unroll
            for (int n8 = 0; n8 < 8; n8++) {
                int c0 = wn * 64 + n8 * 8 + 2 * (lane & 3);
                float b0 = gb[c0], b1 = gb[c0 + 1];
                float s0 = 0.0f, s1 = 0.0f;
#pragma unroll
                for (int mt = 0; mt < 4; mt++) {
                    int gr = pbase + wm * 64 + mt * 16 + (lane >> 2);
                    if (gr < NPAIR) {
                        s0 += fmaxf(acc[mt][n8][0] + b0, 0.0f);
                        s1 += fmaxf(acc[mt][n8][1] + b1, 0.0f);
                    }
                    if (gr + 8 < NPAIR) {
                        s0 += fmaxf(acc[mt][n8][2] + b0, 0.0f);
                        s1 += fmaxf(acc[mt][n8][3] + b1, 0.0f);
                    }
                }
                s0 += __shfl_xor_sync(0xFFFFFFFFu, s0, 4);
                s0 += __shfl_xor_sync(0xFFFFFFFFu, s0, 8);
                s0 += __shfl_xor_sync(0xFFFFFFFFu, s0, 16);
                s1 += __shfl_xor_sync(0xFFFFFFFFu, s1, 4);
                s1 += __shfl_xor_sync(0xFFFFFFFFu, s1, 8);
                s1 += __shfl_xor_sync(0xFFFFFFFFu, s1, 16);
                if (lane < 4) {
                    spart[wm * 256 + c0]     = s0;
                    spart[wm * 256 + c0 + 1] = s1;
                }
            }
            __syncthreads();
            {
                float s = spart[tid] + spart[256 + tid];
                g_partial[(n * NTILE + tile) * GT + tid] = s;
            }
        }
    }
}

// ---------------- reduce partials + f_phi ----------------
__global__ void fphi_kernel(const float* __restrict__ fW0, const float* __restrict__ fb0,
                            const float* __restrict__ fW1, const float* __restrict__ fb1,
                            const float* __restrict__ fW2, const float* __restrict__ fb2,
                            float* __restrict__ out)
{
    int n = blockIdx.x;
    int j = threadIdx.x;
    __shared__ float rs[GT];
    __shared__ float y1[GT];
    __shared__ float y2[GT];

    float s = 0.0f;
    for (int t = 0; t < NTILE; t++)
        s += g_partial[(n * NTILE + t) * GT + j];
    rs[j] = s;
    __syncthreads();

    float h = fb0[j];
#pragma unroll 8
    for (int k = 0; k < GT; k++) h = fmaf(rs[k], fW0[k * GT + j], h);
    y1[j] = fmaxf(h, 0.0f);
    __syncthreads();

    h = fb1[j];
#pragma unroll 8
    for (int k = 0; k < GT; k++) h = fmaf(y1[k], fW1[k * GT + j], h);
    y2[j] = fmaxf(h, 0.0f);
    __syncthreads();

    if (j < AOUT) {
        float o = fb2[j];
#pragma unroll 8
        for (int k = 0; k < GT; k++) o = fmaf(y2[k], fW2[k * AOUT + j], o);
        out[n * AOUT + j] = o;
    }
}

extern "C" void kernel_launch(void* const* d_in, const int* in_sizes, int n_in,
                              void* d_out, int out_size)
{
    const float* x   = (const float*)d_in[0];
    const float* q   = (const float*)d_in[1];
    const float* gW0 = (const float*)d_in[2];
    const float* gb0 = (const float*)d_in[3];
    const float* gW1 = (const float*)d_in[4];
    const float* gb1 = (const float*)d_in[5];
    const float* gW2 = (const float*)d_in[6];
    const float* gb2 = (const float*)d_in[7];
    const float* gW3 = (const float*)d_in[8];
    const float* gb3 = (const float*)d_in[9];
    const float* fW0 = (const float*)d_in[10];
    const float* fb0 = (const float*)d_in[11];
    const float* fW1 = (const float*)d_in[12];
    const float* fb1 = (const float*)d_in[13];
    const float* fW2 = (const float*)d_in[14];
    const float* fb2 = (const float*)d_in[15];
    float* out = (float*)d_out;

    cudaFuncSetAttribute(rn_main, cudaFuncAttributeMaxDynamicSharedMemorySize, SMTOT);

    pairs_kernel<<<(PADP + 255) / 256, 256>>>();
    uv_kernel<<<BN * OO, 256>>>(x, gW0);
    base_kernel<<<BN, 256>>>(q, gW0, gb0);
    prepB_kernel<<<dim3(GT, 3), GT>>>(gW1, gW2, gW3);
    rn_main<<<dim3(NTILE, BN), 256, SMTOT>>>(gb1, gb2, gb3);
    fphi_kernel<<<BN, 256>>>(fW0, fb0, fW1, fb1, fW2, fb2, out);
}

// round 17
// speedup vs baseline: 1.0020x; 1.0006x over previous
#include <cuda_runtime.h>
#include <cuda_bf16.h>
#include <cstdint>

// ---------------- problem constants ----------------
#define BN    32
#define OO    144
#define CP    26
#define GT    256
#define HD    128
#define AOUT  28
#define NPAIR 10440
#define TM    128            // pairs per CTA tile
#define NTILE 82             // ceil(10440/128)
#define PADP  (NTILE*TM)     // 10496

// smem layout (bytes)
#define ASTR  264            // bf16 elems per A row (256 + 8 pad -> +16B skew)
#define BSTR  80             // bytes per B row (64B data + 16B pad)
#define SM_AH 0
#define SM_AL (128*ASTR*2)            // 67584
#define SM_B  (2*128*ASTR*2)          // 135168
#define BTERM (256*BSTR)              // 20480 (one term, one buffer)
#define BBUF  (2*BTERM)               // 40960 (hi+lo)
#define SM_PART (SM_B + 2*BBUF)       // 217088
#define SMTOT   (SM_PART + 2048)      // 219136

typedef unsigned long long u64;

// ---------------- device scratch ----------------
__device__ float g_u[BN*OO*GT];
__device__ float g_v[BN*OO*GT];
__device__ float g_base[BN*GT];
__device__ int   g_pa[PADP];
__device__ int   g_pb[PADP];
__device__ float g_partial[BN*NTILE*GT];
__device__ __nv_bfloat16 g_Bh[3*GT*GT];   // W^T hi, [l][n][k] (K-major)
__device__ __nv_bfloat16 g_Bl[3*GT*GT];   // W^T lo

// ---------------- helpers ----------------
__device__ __forceinline__ uint32_t smem_u32(const void* p) {
    uint32_t a;
    asm("{ .reg .u64 t; cvta.to.shared.u64 t, %1; cvt.u32.u64 %0, t; }" : "=r"(a) : "l"(p));
    return a;
}
__device__ __forceinline__ uint32_t pack2(__nv_bfloat16 a, __nv_bfloat16 b) {
    return (uint32_t)__bfloat16_as_ushort(a) | ((uint32_t)__bfloat16_as_ushort(b) << 16);
}
__device__ __forceinline__ void ldsm4(uint32_t& r0, uint32_t& r1, uint32_t& r2, uint32_t& r3,
                                      uint32_t addr) {
    asm volatile("ldmatrix.sync.aligned.m8n8.x4.shared.b16 {%0,%1,%2,%3}, [%4];"
        : "=r"(r0), "=r"(r1), "=r"(r2), "=r"(r3) : "r"(addr));
}
__device__ __forceinline__ void mma16816(float* d, const uint32_t* a, const uint32_t* b) {
    asm volatile("mma.sync.aligned.m16n8k16.row.col.f32.bf16.bf16.f32 "
        "{%0,%1,%2,%3}, {%4,%5,%6,%7}, {%8,%9}, {%0,%1,%2,%3};"
        : "+f"(d[0]), "+f"(d[1]), "+f"(d[2]), "+f"(d[3])
        : "r"(a[0]), "r"(a[1]), "r"(a[2]), "r"(a[3]), "r"(b[0]), "r"(b[1]));
}
__device__ __forceinline__ void cpa16(uint32_t dst, const void* src) {
    asm volatile("cp.async.cg.shared.global [%0], [%1], 16;" :: "r"(dst), "l"(src));
}
#define CP_COMMIT() asm volatile("cp.async.commit_group;" ::: "memory")

// ---------------- prep kernels ----------------
__global__ void pairs_kernel() {
    int p = blockIdx.x * blockDim.x + threadIdx.x;
    if (p >= PADP) return;
    if (p >= NPAIR) { g_pa[p] = 0; g_pb[p] = 0; return; }
    int a = (int)((sqrtf(8.0f * (float)p + 1.0f) - 1.0f) * 0.5f);
    while ((a + 1) * (a + 2) / 2 <= p) a++;
    while (a * (a + 1) / 2 > p) a--;
    g_pa[p] = a;
    g_pb[p] = p - a * (a + 1) / 2;
}

__global__ void uv_kernel(const float* __restrict__ x, const float* __restrict__ gW0) {
    int n = blockIdx.x / OO;
    int a = blockIdx.x % OO;
    int j = threadIdx.x;
    __shared__ float f[CP];
    if (j < CP) {
        float val;
        if (j < 24)       val = x[((n * 24 + j) * OO) + a];
        else if (j == 24) val = -1.0f + 2.0f * (float)(a / 12) / 11.0f;
        else              val = -1.0f + 2.0f * (float)(a % 12) / 11.0f;
        f[j] = val;
    }
    __syncthreads();
    float u = 0.0f, v = 0.0f;
#pragma unroll
    for (int c = 0; c < CP; c++) {
        float fc = f[c];
        v = fmaf(fc, gW0[c * GT + j], v);
        u = fmaf(fc, gW0[(CP + c) * GT + j], u);
    }
    g_u[(n * OO + a) * GT + j] = u;
    g_v[(n * OO + a) * GT + j] = v;
}

__global__ void base_kernel(const float* __restrict__ q, const float* __restrict__ gW0,
                            const float* __restrict__ gb0) {
    int n = blockIdx.x;
    int j = threadIdx.x;
    float s = gb0[j];
#pragma unroll 8
    for (int k = 0; k < HD; k++)
        s = fmaf(q[n * HD + k], gW0[(2 * CP + k) * GT + j], s);
    g_base[n * GT + j] = s;
}

__global__ void prepB_kernel(const float* __restrict__ gW1, const float* __restrict__ gW2,
                             const float* __restrict__ gW3) {
    int l = blockIdx.y;
    int nrow = blockIdx.x;
    int k = threadIdx.x;
    const float* W = (l == 0) ? gW1 : (l == 1) ? gW2 : gW3;
    float w = W[k * GT + nrow];
    __nv_bfloat16 h = __float2bfloat16(w);
    float r = w - __bfloat162float(h);
    g_Bh[(l * GT + nrow) * GT + k] = h;
    g_Bl[(l * GT + nrow) * GT + k] = __float2bfloat16(r);
}

// ---------------- main HMMA kernel ----------------
__global__ void __launch_bounds__(256, 1) rn_main(
    const float* __restrict__ gb1, const float* __restrict__ gb2,
    const float* __restrict__ gb3)
{
    extern __shared__ char smem[];
    const uint32_t sb = smem_u32(smem);
    const int tid  = threadIdx.x;
    const int lane = tid & 31;
    const int wid  = tid >> 5;
    const int wm   = wid >> 2;      // 0..1  (m half)
    const int wn   = wid & 3;       // 0..3  (n quarter)
    const int tile = blockIdx.x;
    const int n    = blockIdx.y;
    const int pbase = tile * TM;

    __nv_bfloat16* sAh = (__nv_bfloat16*)(smem + SM_AH);
    __nv_bfloat16* sAl = (__nv_bfloat16*)(smem + SM_AL);
    float* spart = (float*)(smem + SM_PART);

    // ---- layer-0 activation build: A[row][k] = relu(u + v + base) ----
    {
        int row = tid & 127;
        int kh  = (tid >> 7) * 128;
        int p = pbase + row;
        const float* up = g_u + (n * OO + g_pa[p]) * GT + kh;
        const float* vp = g_v + (n * OO + g_pb[p]) * GT + kh;
        const float* bp = g_base + n * GT + kh;
        uint32_t* ah = (uint32_t*)(sAh + row * ASTR + kh);
        uint32_t* al = (uint32_t*)(sAl + row * ASTR + kh);
#pragma unroll 8
        for (int k = 0; k < 128; k += 2) {
            float2 uu = *(const float2*)(up + k);
            float2 vv = *(const float2*)(vp + k);
            float2 bb = *(const float2*)(bp + k);
            float f0 = fmaxf(uu.x + vv.x + bb.x, 0.0f);
            float f1 = fmaxf(uu.y + vv.y + bb.y, 0.0f);
            __nv_bfloat16 h0 = __float2bfloat16(f0), h1 = __float2bfloat16(f1);
            float r0 = f0 - __bfloat162float(h0);
            float r1 = f1 - __bfloat162float(h1);
            ah[k >> 1] = pack2(h0, h1);
            al[k >> 1] = pack2(__float2bfloat16(r0), __float2bfloat16(r1));
        }
    }

    float acc[4][8][4];

    // ldmatrix per-lane addressing
    const uint32_t aRow  = (uint32_t)(wm * 64 + (lane & 15));
    const uint32_t aKoff = (uint32_t)((lane >> 4) * 16);           // byte
    const uint32_t bRow  = (uint32_t)(((lane >> 4) & 1) * 8 + (lane & 7));
    const uint32_t bKoff = (uint32_t)(((lane >> 3) & 1) * 16);     // byte

    for (int layer = 0; layer < 3; layer++) {
        const __nv_bfloat16* Bh = g_Bh + layer * GT * GT;
        const __nv_bfloat16* Bl = g_Bl + layer * GT * GT;
        const float* gb = (layer == 0) ? gb1 : (layer == 1) ? gb2 : gb3;

#pragma unroll
        for (int mt = 0; mt < 4; mt++)
#pragma unroll
            for (int n8 = 0; n8 < 8; n8++)
#pragma unroll
                for (int r = 0; r < 4; r++) acc[mt][n8][r] = 0.0f;

        // chunk loader: 256 rows x 32 k (64B) for hi and lo
        auto load_chunk = [&](int kc) {
            uint32_t dbase = sb + SM_B + (uint32_t)((kc & 1) * BBUF);
#pragma unroll
            for (int i = 0; i < 4; i++) {
                int v = tid + i * 256;
                int row = v >> 2, seg = v & 3;
                uint32_t d = dbase + (uint32_t)(row * BSTR + seg * 16);
                cpa16(d,         Bh + row * GT + kc * 32 + seg * 8);
                cpa16(d + BTERM, Bl + row * GT + kc * 32 + seg * 8);
            }
            CP_COMMIT();
        };

        load_chunk(0);
        load_chunk(1);

        for (int kc = 0; kc < 8; kc++) {
            if (kc < 7) { asm volatile("cp.async.wait_group 1;" ::: "memory"); }
            else        { asm volatile("cp.async.wait_group 0;" ::: "memory"); }
            __syncthreads();

            uint32_t bbase = sb + SM_B + (uint32_t)((kc & 1) * BBUF);
#pragma unroll
            for (int s = 0; s < 2; s++) {
                uint32_t ah[4][4], al[4][4], bh[8][2], bl[8][2];
                uint32_t kb = (uint32_t)(kc * 64 + s * 32) + aKoff;

                // B hi frags
#pragma unroll
                for (int ntp = 0; ntp < 4; ntp++) {
                    uint32_t addr = bbase + (uint32_t)((wn * 64 + ntp * 16) + bRow) * BSTR
                                  + (uint32_t)(s * 32) + bKoff;
                    ldsm4(bh[2*ntp][0], bh[2*ntp][1], bh[2*ntp+1][0], bh[2*ntp+1][1], addr);
                }
                // A hi frags
#pragma unroll
                for (int mt = 0; mt < 4; mt++) {
                    uint32_t addr = sb + SM_AH + ((aRow + (uint32_t)(mt * 16)) * ASTR) * 2 + kb;
                    ldsm4(ah[mt][0], ah[mt][1], ah[mt][2], ah[mt][3], addr);
                }
                // term 1: Ah * Bh
#pragma unroll
                for (int mt = 0; mt < 4; mt++)
#pragma unroll
                    for (int n8 = 0; n8 < 8; n8++) mma16816(acc[mt][n8], ah[mt], bh[n8]);
                // B lo frags + term 3: Ah * Bl
#pragma unroll
                for (int ntp = 0; ntp < 4; ntp++) {
                    uint32_t addr = bbase + (uint32_t)((wn * 64 + ntp * 16) + bRow) * BSTR
                                  + (uint32_t)(s * 32) + bKoff + BTERM;
                    ldsm4(bl[2*ntp][0], bl[2*ntp][1], bl[2*ntp+1][0], bl[2*ntp+1][1], addr);
                }
#pragma unroll
                for (int mt = 0; mt < 4; mt++)
#pragma unroll
                    for (int n8 = 0; n8 < 8; n8++) mma16816(acc[mt][n8], ah[mt], bl[n8]);
                // A lo frags + term 2: Al * Bh
#pragma unroll
                for (int mt = 0; mt < 4; mt++) {
                    uint32_t addr = sb + SM_AH + ((aRow + (uint32_t)(mt * 16)) * ASTR) * 2 + kb
                                  + SM_AL;
                    ldsm4(al[mt][0], al[mt][1], al[mt][2], al[mt][3], addr);
                }
#pragma unroll
                for (int mt = 0; mt < 4; mt++)
#pragma unroll
                    for (int n8 = 0; n8 < 8; n8++) mma16816(acc[mt][n8], al[mt], bh[n8]);
            }
            __syncthreads();
            if (kc + 2 < 8) load_chunk(kc + 2);
        }

        if (layer < 2) {
            // epilogue: relu(D + bias) -> hi/lo bf16 -> back into sA
#pragma unroll
            for (int n8 = 0; n8 < 8; n8++) {
                int c0 = wn * 64 + n8 * 8 + 2 * (lane & 3);
                float b0 = gb[c0], b1 = gb[c0 + 1];
#pragma unroll
                for (int mt = 0; mt < 4; mt++) {
                    int r0 = wm * 64 + mt * 16 + (lane >> 2);
                    float f00 = fmaxf(acc[mt][n8][0] + b0, 0.0f);
                    float f01 = fmaxf(acc[mt][n8][1] + b1, 0.0f);
                    float f10 = fmaxf(acc[mt][n8][2] + b0, 0.0f);
                    float f11 = fmaxf(acc[mt][n8][3] + b1, 0.0f);
                    __nv_bfloat16 h00 = __float2bfloat16(f00), h01 = __float2bfloat16(f01);
                    __nv_bfloat16 h10 = __float2bfloat16(f10), h11 = __float2bfloat16(f11);
                    *(uint32_t*)(sAh + r0 * ASTR + c0)       = pack2(h00, h01);
                    *(uint32_t*)(sAh + (r0 + 8) * ASTR + c0) = pack2(h10, h11);
                    *(uint32_t*)(sAl + r0 * ASTR + c0)       =
                        pack2(__float2bfloat16(f00 - __bfloat162float(h00)),
                              __float2bfloat16(f01 - __bfloat162float(h01)));
                    *(uint32_t*)(sAl + (r0 + 8) * ASTR + c0) =
                        pack2(__float2bfloat16(f10 - __bfloat162float(h10)),
                              __float2bfloat16(f11 - __bfloat162float(h11)));
                }
            }
            // visibility guaranteed by the __syncthreads after kc=0's wait next layer
        } else {
            // final layer: relu+bias, mask rows >= NPAIR, column-sum over 128 rows
#pragma unroll
            for (int n8 = 0; n8 < 8; n8++) {
                int c0 = wn * 64 + n8 * 8 + 2 * (lane & 3);
                float b0 = gb[c0], b1 = gb[c0 + 1];
                float s0 = 0.0f, s1 = 0.0f;
#pragma unroll
                for (int mt = 0; mt < 4; mt++) {
                    int gr = pbase + wm * 64 + mt * 16 + (lane >> 2);
                    if (gr < NPAIR) {
                        s0 += fmaxf(acc[mt][n8][0] + b0, 0.0f);
                        s1 += fmaxf(acc[mt][n8][1] + b1, 0.0f);
                    }
                    if (gr + 8 < NPAIR) {
                        s0 += fmaxf(acc[mt][n8][2] + b0, 0.0f);
                        s1 += fmaxf(acc[mt][n8][3] + b1, 0.0f);
                    }
                }
                s0 += __shfl_xor_sync(0xFFFFFFFFu, s0, 4);
                s0 += __shfl_xor_sync(0xFFFFFFFFu, s0, 8);
                s0 += __shfl_xor_sync(0xFFFFFFFFu, s0, 16);
                s1 += __shfl_xor_sync(0xFFFFFFFFu, s1, 4);
                s1 += __shfl_xor_sync(0xFFFFFFFFu, s1, 8);
                s1 += __shfl_xor_sync(0xFFFFFFFFu, s1, 16);
                if (lane < 4) {
                    spart[wm * 256 + c0]     = s0;
                    spart[wm * 256 + c0 + 1] = s1;
                }
            }
            __syncthreads();
            {
                float s = spart[tid] + spart[256 + tid];
                g_partial[(n * NTILE + tile) * GT + tid] = s;
            }
        }
    }
}

// ---------------- reduce partials + f_phi ----------------
__global__ void fphi_kernel(const float* __restrict__ fW0, const float* __restrict__ fb0,
                            const float* __restrict__ fW1, const float* __restrict__ fb1,
                            const float* __restrict__ fW2, const float* __restrict__ fb2,
                            float* __restrict__ out)
{
    int n = blockIdx.x;
    int j = threadIdx.x;
    __shared__ float rs[GT];
    __shared__ float y1[GT];
    __shared__ float y2[GT];

    float s = 0.0f;
    for (int t = 0; t < NTILE; t++)
        s += g_partial[(n * NTILE + t) * GT + j];
    rs[j] = s;
    __syncthreads();

    float h = fb0[j];
#pragma unroll 8
    for (int k = 0; k < GT; k++) h = fmaf(rs[k], fW0[k * GT + j], h);
    y1[j] = fmaxf(h, 0.0f);
    __syncthreads();

    h = fb1[j];
#pragma unroll 8
    for (int k = 0; k < GT; k++) h = fmaf(y1[k], fW1[k * GT + j], h);
    y2[j] = fmaxf(h, 0.0f);
    __syncthreads();

    if (j < AOUT) {
        float o = fb2[j];
#pragma unroll 8
        for (int k = 0; k < GT; k++) o = fmaf(y2[k], fW2[k * AOUT + j], o);
        out[n * AOUT + j] = o;
    }
}

extern "C" void kernel_launch(void* const* d_in, const int* in_sizes, int n_in,
                              void* d_out, int out_size)
{
    const float* x   = (const float*)d_in[0];
    const float* q   = (const float*)d_in[1];
    const float* gW0 = (const float*)d_in[2];
    const float* gb0 = (const float*)d_in[3];
    const float* gW1 = (const float*)d_in[4];
    const float* gb1 = (const float*)d_in[5];
    const float* gW2 = (const float*)d_in[6];
    const float* gb2 = (const float*)d_in[7];
    const float* gW3 = (const float*)d_in[8];
    const float* gb3 = (const float*)d_in[9];
    const float* fW0 = (const float*)d_in[10];
    const float* fb0 = (const float*)d_in[11];
    const float* fW1 = (const float*)d_in[12];
    const float* fb1 = (const float*)d_in[13];
    const float* fW2 = (const float*)d_in[14];
    const float* fb2 = (const float*)d_in[15];
    float* out = (float*)d_out;

    cudaFuncSetAttribute(rn_main, cudaFuncAttributeMaxDynamicSharedMemorySize, SMTOT);

    pairs_kernel<<<(PADP + 255) / 256, 256>>>();
    uv_kernel<<<BN * OO, 256>>>(x, gW0);
    base_kernel<<<BN, 256>>>(q, gW0, gb0);
    prepB_kernel<<<dim3(GT, 3), GT>>>(gW1, gW2, gW3);
    rn_main<<<dim3(NTILE, BN), 256, SMTOT>>>(gb1, gb2, gb3);
    fphi_kernel<<<BN, 256>>>(fW0, fb0, fW1, fb1, fW2, fb2, out);
}